// round 4
// baseline (speedup 1.0000x reference)
#include <cuda_runtime.h>
#include <cuda_fp16.h>

// Problem constants
#define Bb    4
#define Tt    16
#define Hh    64
#define Ww    64
#define Cc    256
#define NCLS  512
#define TAPS  27
#define WCHUNK 32
#define WOFF_BYTES (TAPS * Cc * 2)   // 13824 bytes per class row-block

// Transposed fp16 weight table: [class][tap][channel]
__device__ __align__(16) __half g_wt[NCLS * TAPS * Cc];

// ---------------------------------------------------------------------------
// Kernel A: transpose + fp16 convert, smem-tiled so both sides are coalesced.
// ---------------------------------------------------------------------------
__global__ void __launch_bounds__(256) wt_transpose_kernel(const float* __restrict__ w)
{
    __shared__ float s[32 * 27];
    const int bx  = blockIdx.x;
    const int n   = bx >> 3;
    const int c0  = (bx & 7) * 32;
    const int tid = threadIdx.x;

    for (int i = tid; i < 32 * 27; i += 256) {
        int cl = i / 27, k = i % 27;
        s[i] = w[(size_t)(c0 + cl) * (NCLS * TAPS) + n * TAPS + k];
    }
    __syncthreads();
    for (int j = tid; j < 32 * 27; j += 256) {
        int k = j >> 5, cl = j & 31;
        g_wt[(n * TAPS + k) * Cc + c0 + cl] = __float2half_rn(s[cl * 27 + k]);
    }
}

// ---------------------------------------------------------------------------
// Kernel B: gather-accumulate. Same structure as R3 (which passed at 197us)
// but reg-capped to 51 via __launch_bounds__(256, 5): R3 ran at 56 regs ->
// only 4 blocks/SM (32/64 warps); the profile showed L1=75%, L2=74%,
// issue=53% -> latency-exposed, occupancy-bound. 5 blocks -> 40 warps.
// ---------------------------------------------------------------------------
__global__ void __launch_bounds__(256, 5) onehot_conv_kernel(
    const int*   __restrict__ indices,
    const float* __restrict__ bias,
    float*       __restrict__ out)
{
    __shared__ __align__(16) float4 s_stage[WCHUNK * 64];   // [w][quad], swizzled, 32KB
    __shared__ int s_off[9 * 34];                           // class byte-offsets, halo'd in w

    const int bx   = blockIdx.x;
    const int wblk = bx & 1;
    const int h    = (bx >> 1) & 63;
    const int t    = (bx >> 7) & 15;
    const int b    = bx >> 11;
    const int w0   = wblk * WCHUNK;
    const int tid  = threadIdx.x;

    // Halo of class byte-offsets: 9 (dt,dh) rows x 34 w, edge-clamped.
    for (int i = tid; i < 9 * 34; i += 256) {
        int r  = i / 34, j = i % 34;
        int dt = r / 3,  dh = r % 3;
        int st = t + dt - 2; if (st < 0) st = 0;
        int sh = h + dh - 1; if (sh < 0) sh = 0; if (sh > Hh - 1) sh = Hh - 1;
        int gw = w0 + j - 1; if (gw < 0) gw = 0; if (gw > Ww - 1) gw = Ww - 1;
        s_off[i] = indices[((b * Tt + st) * Hh + sh) * Ww + gw] * WOFF_BYTES;
    }
    __syncthreads();

    const int warp = tid >> 5;
    const int lane = tid & 31;
    const int kl   = lane < 27 ? lane : 26;     // lane -> tap (guarded)
    const int rIdx = (kl / 3) * 34 + (kl % 3);  // row part of s_off index

    const char* wtb   = reinterpret_cast<const char*>(g_wt);
    const char* base0 = wtb + lane * 8;               // channels 4l..4l+3
    const char* base1 = wtb + 256 + lane * 8;         // channels 128+4l..

    const float4 bz0 = *reinterpret_cast<const float4*>(bias + 4 * lane);
    const float4 bz1 = *reinterpret_cast<const float4*>(bias + 128 + 4 * lane);

    #pragma unroll 1
    for (int p = 0; p < 4; p++) {
        const int w_l = p * 8 + warp;
        // each lane holds the class byte-offset for tap `lane` at this position
        const int myoff = s_off[rIdx + w_l];

        float4 a0 = bz0, a1 = bz1;

        #pragma unroll
        for (int k = 0; k < 26; k += 2) {
            const int o0 = __shfl_sync(0xffffffffu, myoff, k);
            const int o1 = __shfl_sync(0xffffffffu, myoff, k + 1);
            uint2 u0a = *reinterpret_cast<const uint2*>(base0 + o0 + k * 512);
            uint2 u0b = *reinterpret_cast<const uint2*>(base1 + o0 + k * 512);
            uint2 u1a = *reinterpret_cast<const uint2*>(base0 + o1 + (k + 1) * 512);
            uint2 u1b = *reinterpret_cast<const uint2*>(base1 + o1 + (k + 1) * 512);
            __half2 s0 = __hadd2(*reinterpret_cast<__half2*>(&u0a.x), *reinterpret_cast<__half2*>(&u1a.x));
            __half2 s1 = __hadd2(*reinterpret_cast<__half2*>(&u0a.y), *reinterpret_cast<__half2*>(&u1a.y));
            __half2 s2 = __hadd2(*reinterpret_cast<__half2*>(&u0b.x), *reinterpret_cast<__half2*>(&u1b.x));
            __half2 s3 = __hadd2(*reinterpret_cast<__half2*>(&u0b.y), *reinterpret_cast<__half2*>(&u1b.y));
            float2 f;
            f = __half22float2(s0); a0.x += f.x; a0.y += f.y;
            f = __half22float2(s1); a0.z += f.x; a0.w += f.y;
            f = __half22float2(s2); a1.x += f.x; a1.y += f.y;
            f = __half22float2(s3); a1.z += f.x; a1.w += f.y;
        }
        {   // tap 26 (unpaired)
            const int o = __shfl_sync(0xffffffffu, myoff, 26);
            uint2 ua = *reinterpret_cast<const uint2*>(base0 + o + 26 * 512);
            uint2 ub = *reinterpret_cast<const uint2*>(base1 + o + 26 * 512);
            float2 f;
            f = __half22float2(*reinterpret_cast<__half2*>(&ua.x)); a0.x += f.x; a0.y += f.y;
            f = __half22float2(*reinterpret_cast<__half2*>(&ua.y)); a0.z += f.x; a0.w += f.y;
            f = __half22float2(*reinterpret_cast<__half2*>(&ub.x)); a1.x += f.x; a1.y += f.y;
            f = __half22float2(*reinterpret_cast<__half2*>(&ub.y)); a1.z += f.x; a1.w += f.y;
        }

        // XOR-swizzled store: logical quad q at phys q^(w&31); conflict-free.
        const int sw = w_l & 31;
        s_stage[w_l * 64 + (lane ^ sw)]        = a0;
        s_stage[w_l * 64 + 32 + (lane ^ sw)]   = a1;
    }
    __syncthreads();

    // Read-back: warp takes logical quads qq = warp, warp+8, ...; lane = w.
    const size_t THW   = (size_t)Tt * Hh * Ww;
    const size_t obase = (size_t)b * Cc * THW + (size_t)t * (Hh * Ww) + (size_t)h * Ww + w0;
    #pragma unroll
    for (int qq = warp; qq < 64; qq += 8) {
        float4 v = s_stage[lane * 64 + (qq ^ (lane & 31))];
        const int c = qq * 4;
        out[obase + (size_t)(c + 0) * THW + lane] = v.x;
        out[obase + (size_t)(c + 1) * THW + lane] = v.y;
        out[obase + (size_t)(c + 2) * THW + lane] = v.z;
        out[obase + (size_t)(c + 3) * THW + lane] = v.w;
    }
}

// ---------------------------------------------------------------------------
extern "C" void kernel_launch(void* const* d_in, const int* in_sizes, int n_in,
                              void* d_out, int out_size)
{
    const int*   indices = (const int*)  d_in[0];
    const float* weight  = (const float*)d_in[1];
    const float* bias    = (const float*)d_in[2];
    float*       out     = (float*)d_out;

    wt_transpose_kernel<<<NCLS * (Cc / 32), 256>>>(weight);

    const int grid = Bb * Tt * Hh * (Ww / WCHUNK);   // 8192
    onehot_conv_kernel<<<grid, 256>>>(indices, bias, out);
}

// round 5
// speedup vs baseline: 1.0275x; 1.0275x over previous
#include <cuda_runtime.h>
#include <cuda_fp16.h>

// Problem constants
#define Bb    4
#define Tt    16
#define Hh    64
#define Ww    64
#define Cc    256
#define NCLS  512
#define TAPS  27
#define WCHUNK 32
#define WOFF_BYTES (TAPS * Cc * 2)   // 13824 bytes per class row-block

// Transposed fp16 weight table: [class][tap][channel]
__device__ __align__(16) __half g_wt[NCLS * TAPS * Cc];

// ---------------------------------------------------------------------------
// Kernel A: transpose + fp16 convert, smem-tiled so both sides are coalesced.
// ---------------------------------------------------------------------------
__global__ void __launch_bounds__(256) wt_transpose_kernel(const float* __restrict__ w)
{
    __shared__ float s[32 * 27];
    const int bx  = blockIdx.x;
    const int n   = bx >> 3;
    const int c0  = (bx & 7) * 32;
    const int tid = threadIdx.x;

    for (int i = tid; i < 32 * 27; i += 256) {
        int cl = i / 27, k = i % 27;
        s[i] = w[(size_t)(c0 + cl) * (NCLS * TAPS) + n * TAPS + k];
    }
    __syncthreads();
    for (int j = tid; j < 32 * 27; j += 256) {
        int k = j >> 5, cl = j & 31;
        g_wt[(n * TAPS + k) * Cc + c0 + cl] = __float2half_rn(s[cl * 27 + k]);
    }
}

// ---------------------------------------------------------------------------
// Kernel B: gather-accumulate, LDG.128 variant.
// Warp owns one position per pass; lane owns channels 8l..8l+7, so ONE
// LDG.128 per tap fetches the whole 512B row warp-wide (R4 used 2x LDG.64:
// same bytes but half the bytes-in-flight per load-queue slot and 2x the
// LSU dispatches). Taps paired with HADD2 in fp16 before fp32 accumulate.
// ---------------------------------------------------------------------------
__global__ void __launch_bounds__(256, 5) onehot_conv_kernel(
    const int*   __restrict__ indices,
    const float* __restrict__ bias,
    float*       __restrict__ out)
{
    __shared__ __align__(16) float4 s_stage[WCHUNK * 64];   // [w][quad], swizzled, 32KB
    __shared__ int s_off[9 * 34];                           // class byte-offsets, halo'd in w

    const int bx   = blockIdx.x;
    const int wblk = bx & 1;
    const int h    = (bx >> 1) & 63;
    const int t    = (bx >> 7) & 15;
    const int b    = bx >> 11;
    const int w0   = wblk * WCHUNK;
    const int tid  = threadIdx.x;

    // Halo of class byte-offsets: 9 (dt,dh) rows x 34 w, edge-clamped.
    for (int i = tid; i < 9 * 34; i += 256) {
        int r  = i / 34, j = i % 34;
        int dt = r / 3,  dh = r % 3;
        int st = t + dt - 2; if (st < 0) st = 0;
        int sh = h + dh - 1; if (sh < 0) sh = 0; if (sh > Hh - 1) sh = Hh - 1;
        int gw = w0 + j - 1; if (gw < 0) gw = 0; if (gw > Ww - 1) gw = Ww - 1;
        s_off[i] = indices[((b * Tt + st) * Hh + sh) * Ww + gw] * WOFF_BYTES;
    }
    __syncthreads();

    const int warp = tid >> 5;
    const int lane = tid & 31;
    const int kl   = lane < 27 ? lane : 26;     // lane -> tap (guarded)
    const int rIdx = (kl / 3) * 34 + (kl % 3);  // row part of s_off index

    const char* wtb  = reinterpret_cast<const char*>(g_wt);
    const char* base = wtb + lane * 16;          // this lane's 8 channels (fp16 x8 = 16B)

    const float4 bz0 = *reinterpret_cast<const float4*>(bias + 8 * lane);
    const float4 bz1 = *reinterpret_cast<const float4*>(bias + 8 * lane + 4);

    #pragma unroll 1
    for (int p = 0; p < 4; p++) {
        const int w_l = p * 8 + warp;
        // each lane holds the class byte-offset for tap `lane` at this position
        const int myoff = s_off[rIdx + w_l];

        float4 a0 = bz0, a1 = bz1;

        #pragma unroll
        for (int k = 0; k < 26; k += 2) {
            const int o0 = __shfl_sync(0xffffffffu, myoff, k);
            const int o1 = __shfl_sync(0xffffffffu, myoff, k + 1);
            uint4 u0 = *reinterpret_cast<const uint4*>(base + o0 + k * 512);
            uint4 u1 = *reinterpret_cast<const uint4*>(base + o1 + (k + 1) * 512);
            __half2 s0 = __hadd2(*reinterpret_cast<__half2*>(&u0.x), *reinterpret_cast<__half2*>(&u1.x));
            __half2 s1 = __hadd2(*reinterpret_cast<__half2*>(&u0.y), *reinterpret_cast<__half2*>(&u1.y));
            __half2 s2 = __hadd2(*reinterpret_cast<__half2*>(&u0.z), *reinterpret_cast<__half2*>(&u1.z));
            __half2 s3 = __hadd2(*reinterpret_cast<__half2*>(&u0.w), *reinterpret_cast<__half2*>(&u1.w));
            float2 f;
            f = __half22float2(s0); a0.x += f.x; a0.y += f.y;
            f = __half22float2(s1); a0.z += f.x; a0.w += f.y;
            f = __half22float2(s2); a1.x += f.x; a1.y += f.y;
            f = __half22float2(s3); a1.z += f.x; a1.w += f.y;
        }
        {   // tap 26 (unpaired)
            const int o = __shfl_sync(0xffffffffu, myoff, 26);
            uint4 u = *reinterpret_cast<const uint4*>(base + o + 26 * 512);
            float2 f;
            f = __half22float2(*reinterpret_cast<__half2*>(&u.x)); a0.x += f.x; a0.y += f.y;
            f = __half22float2(*reinterpret_cast<__half2*>(&u.y)); a0.z += f.x; a0.w += f.y;
            f = __half22float2(*reinterpret_cast<__half2*>(&u.z)); a1.x += f.x; a1.y += f.y;
            f = __half22float2(*reinterpret_cast<__half2*>(&u.w)); a1.z += f.x; a1.w += f.y;
        }

        // Lane l holds logical quads 2l (a0) and 2l+1 (a1).
        // Permute: quad 2l -> col l, quad 2l+1 -> col 32+l, XOR-swizzled by w.
        // Store addresses are lane-linear ^ const -> conflict-free STS.128.
        const int sw = w_l & 31;
        s_stage[w_l * 64 + (lane ^ sw)]        = a0;
        s_stage[w_l * 64 + 32 + (lane ^ sw)]   = a1;
    }
    __syncthreads();

    // Read-back: logical quad qq = 2l+e lives at phys col e*32 + l.
    // lane = w; per-lane bank index = (p ^ (lane&31)) -> conflict-free LDS.128.
    const size_t THW   = (size_t)Tt * Hh * Ww;
    const size_t obase = (size_t)b * Cc * THW + (size_t)t * (Hh * Ww) + (size_t)h * Ww + w0;
    #pragma unroll
    for (int qq = warp; qq < 64; qq += 8) {
        const int pcol = ((qq & 1) << 5) | (qq >> 1);
        float4 v = s_stage[lane * 64 + (pcol ^ (lane & 31))];
        const int c = qq * 4;
        out[obase + (size_t)(c + 0) * THW + lane] = v.x;
        out[obase + (size_t)(c + 1) * THW + lane] = v.y;
        out[obase + (size_t)(c + 2) * THW + lane] = v.z;
        out[obase + (size_t)(c + 3) * THW + lane] = v.w;
    }
}

// ---------------------------------------------------------------------------
extern "C" void kernel_launch(void* const* d_in, const int* in_sizes, int n_in,
                              void* d_out, int out_size)
{
    const int*   indices = (const int*)  d_in[0];
    const float* weight  = (const float*)d_in[1];
    const float* bias    = (const float*)d_in[2];
    float*       out     = (float*)d_out;

    wt_transpose_kernel<<<NCLS * (Cc / 32), 256>>>(weight);

    const int grid = Bb * Tt * Hh * (Ww / WCHUNK);   // 8192
    onehot_conv_kernel<<<grid, 256>>>(indices, bias, out);
}